// round 16
// baseline (speedup 1.0000x reference)
#include <cuda_runtime.h>
#include <cuda_bf16.h>

// ---------------- problem constants ----------------
#define N_A   30000
#define N_B   30000
#define VV    2
#define DD    128
#define EE    480000
#define PP    2

#define ROWS_H 60000    // N_A*V   (also N_B*V)
#define ROWS_X 120000   // N_A*V*P

// mma kernels: blocked bf16 tiles. W tile = 32768 B (hi or lo). A stage = 8192 B.
#define SMEM_PROJ_MMA (4*32768 + 8*8192 + 6*512)  // 199680
#define PROJ_AOFF     (4*32768)
#define PROJ_BOFF2    (4*32768 + 8*8192)
#define SMEM_OUT_MMA  (2*32768 + 8*8192 + 3*512)  // 132608
#define OUT_AOFF      (2*32768)
#define OUT_BOFF2     (2*32768 + 8*8192)
// qkv: 3 weights hi/lo (192KB) + 4 pair-shared A stages (32KB) + 3 biases
#define SMEM_QKV_MMA  (6*32768 + 4*8192 + 3*512)  // 230912 (<= 232448)
#define QKV_AOFF      (6*32768)
#define QKV_BOFF      (6*32768 + 4*8192)

#define GRID_GEMM 148

typedef unsigned long long u64;

// ---------------- scratch (device globals; no allocation allowed) ----------------
__device__ int g_cnt_ab[N_B];     // zero at module load; re-zeroed by k_scan each run
__device__ int g_cnt_ba[N_A];
__device__ int g_ptr_ab[N_B + 1];
__device__ int g_ptr_ba[N_A + 1];
__device__ int g_cur_ab[N_B];     // scatter cursors (rebuilt by k_scan each run)
__device__ int g_cur_ba[N_A];
__device__ int   g_srcs_ab[EE];
__device__ float g_vals_ab[EE];
__device__ int   g_srcs_ba[EE];
__device__ float g_vals_ba[EE];

__device__ float g_hB  [(size_t)N_B * VV * DD];
__device__ float g_hABA[(size_t)N_A * VV * DD];
__device__ float g_hBA [(size_t)N_A * VV * DD];
__device__ float g_x[(size_t)ROWS_X * DD];
__device__ float g_o[(size_t)ROWS_X * DD];

// ---------------- generic helpers ----------------
static __device__ __forceinline__ float warp_sum(float v) {
#pragma unroll
    for (int o = 16; o > 0; o >>= 1) v += __shfl_xor_sync(0xffffffffu, v, o);
    return v;
}
static __device__ __forceinline__ unsigned smem_u32(const void* p) {
    unsigned a;
    asm("{ .reg .u64 t; cvta.to.shared.u64 t, %1; cvt.u32.u64 %0, t; }" : "=r"(a) : "l"(p));
    return a;
}

// ---------------- mma.sync helpers (sm_80-baseline ISA) ----------------
static __device__ __forceinline__ void ldsm4(unsigned* r, unsigned addr) {
    asm volatile("ldmatrix.sync.aligned.m8n8.x4.shared.b16 {%0,%1,%2,%3}, [%4];"
                 : "=r"(r[0]), "=r"(r[1]), "=r"(r[2]), "=r"(r[3]) : "r"(addr));
}
static __device__ __forceinline__ void mma16816(float* d, const unsigned* a,
                                                unsigned b0, unsigned b1) {
    asm volatile("mma.sync.aligned.m16n8k16.row.col.f32.bf16.bf16.f32 "
                 "{%0,%1,%2,%3}, {%4,%5,%6,%7}, {%8,%9}, {%0,%1,%2,%3};"
                 : "+f"(d[0]), "+f"(d[1]), "+f"(d[2]), "+f"(d[3])
                 : "r"(a[0]), "r"(a[1]), "r"(a[2]), "r"(a[3]), "r"(b0), "r"(b1));
}

static __device__ __forceinline__ unsigned short bf_bits(__nv_bfloat16 h) {
    return *reinterpret_cast<unsigned short*>(&h);
}
// float4 -> packed bf16 hi (u64) + lo (u64)
static __device__ __forceinline__ void split4(float4 f, u64& hi, u64& lo) {
    __nv_bfloat16 h0 = __float2bfloat16(f.x), h1 = __float2bfloat16(f.y);
    __nv_bfloat16 h2 = __float2bfloat16(f.z), h3 = __float2bfloat16(f.w);
    __nv_bfloat16 l0 = __float2bfloat16(f.x - __bfloat162float(h0));
    __nv_bfloat16 l1 = __float2bfloat16(f.y - __bfloat162float(h1));
    __nv_bfloat16 l2 = __float2bfloat16(f.z - __bfloat162float(h2));
    __nv_bfloat16 l3 = __float2bfloat16(f.w - __bfloat162float(h3));
    hi = (u64)bf_bits(h0) | ((u64)bf_bits(h1) << 16)
       | ((u64)bf_bits(h2) << 32) | ((u64)bf_bits(h3) << 48);
    lo = (u64)bf_bits(l0) | ((u64)bf_bits(l1) << 16)
       | ((u64)bf_bits(l2) << 32) | ((u64)bf_bits(l3) << 48);
}

// Stage W (128x128 f32) into PAIR-BLOCKED bf16 B-tiles:
// group (nbp, kb) = 512 B holding 4 sub8x8: [nb0 kc0][nb0 kc1][nb1 kc0][nb1 kc1]
// element (j, kc): off = (nbp*8+kb)*512 + (p*2+kcs)*128 + (j&7)*16 + (kc&7)*2
//   nbp=j>>4, p=(j>>3)&1, kb=kc>>4, kcs=(kc>>3)&1
// ldmatrix.x4 at group base + lane*16 -> {b0,b1} for nb0, {b2,b3} for nb1.
static __device__ __forceinline__ void stage_W(char* smc, int off_hi, int off_lo,
                                               const float* W, int tid, int nthreads) {
    for (int idx = tid; idx < 4096; idx += nthreads) {
        int j = idx >> 5;
        int kq = (idx & 31) << 2;
        float4 f = *reinterpret_cast<const float4*>(W + j * DD + kq);
        u64 hi, lo; split4(f, hi, lo);
        unsigned off = (unsigned)((((j >> 4) * 8 + (kq >> 4)) * 512) +
                                  ((((j >> 3) & 1) * 2 + ((kq >> 3) & 1)) * 128) +
                                  ((j & 7) * 16) + ((kq & 7) * 2));
        *reinterpret_cast<u64*>(smc + off_hi + off) = hi;
        *reinterpret_cast<u64*>(smc + off_lo + off) = lo;
    }
}

// Stage 16x128 f32 rows into blocked bf16 hi/lo A-tiles (one warp, 32 lanes).
static __device__ __forceinline__ void stage_A16(char* smc, int off_hi, int off_lo,
                                                 const float* src, int lane) {
#pragma unroll
    for (int i = 0; i < 16; i++) {
        int idx = lane + i * 32;
        int r = idx >> 5;
        int kq = (idx & 31) << 2;
        float4 f = *reinterpret_cast<const float4*>(src + (size_t)r * DD + kq);
        u64 hi, lo; split4(f, hi, lo);
        unsigned off = (unsigned)(((kq >> 4) * 512) +
                                  ((((r >> 3) | (((kq >> 3) & 1) << 1))) * 128) +
                                  ((r & 7) * 16) + ((kq & 7) * 2));
        *reinterpret_cast<u64*>(smc + off_hi + off) = hi;
        *reinterpret_cast<u64*>(smc + off_lo + off) = lo;
    }
}

// 3-pass bf16-split GEMM core with ldsm4 B-pair loads
static __device__ __forceinline__ void mma_core(float acc[16][4],
                                                unsigned aBaseH, unsigned aBaseL,
                                                unsigned wH, unsigned wL, int lane) {
    unsigned ah[8][4], al[8][4];
#pragma unroll
    for (int kb = 0; kb < 8; kb++) {
        ldsm4(ah[kb], aBaseH + kb * 512 + lane * 16);
        ldsm4(al[kb], aBaseL + kb * 512 + lane * 16);
    }
#pragma unroll
    for (int kb = 0; kb < 8; kb++) {
#pragma unroll
        for (int nbp = 0; nbp < 8; nbp++) {
            unsigned boff = (unsigned)((nbp * 8 + kb) * 512 + lane * 16);
            unsigned bh[4], bl[4];
            ldsm4(bh, wH + boff);
            ldsm4(bl, wL + boff);
            mma16816(acc[2 * nbp],     ah[kb], bh[0], bh[1]);
            mma16816(acc[2 * nbp + 1], ah[kb], bh[2], bh[3]);
            mma16816(acc[2 * nbp],     ah[kb], bl[0], bl[1]);
            mma16816(acc[2 * nbp + 1], ah[kb], bl[2], bl[3]);
            mma16816(acc[2 * nbp],     al[kb], bh[0], bh[1]);
            mma16816(acc[2 * nbp + 1], al[kb], bh[2], bh[3]);
        }
    }
}

// ---------------- CSR build (no zero launches) ----------------
__global__ void k_hist(const int* __restrict__ dst_ab, const int* __restrict__ dst_ba) {
    int e = blockIdx.x * blockDim.x + threadIdx.x;
    if (e < EE) {
        atomicAdd(&g_cnt_ab[dst_ab[e]], 1);
        atomicAdd(&g_cnt_ba[dst_ba[e]], 1);
    }
}

// scan: cnt -> ptr (+cursor copy), then zero cnt for the next replay
__global__ void k_scan() {
    __shared__ int ssum[1024];
    const int n = N_A;
    int* cnt = (blockIdx.x == 0) ? g_cnt_ab : g_cnt_ba;
    int* ptr = (blockIdx.x == 0) ? g_ptr_ab : g_ptr_ba;
    int* cur = (blockIdx.x == 0) ? g_cur_ab : g_cur_ba;
    int t = threadIdx.x;
    const int chunk = (n + 1023) / 1024;
    int b0 = t * chunk;
    int b1 = min(b0 + chunk, n);
    int s = 0;
    for (int i = b0; i < b1; i++) s += cnt[i];
    ssum[t] = s;
    __syncthreads();
#pragma unroll
    for (int off = 1; off < 1024; off <<= 1) {
        int v = (t >= off) ? ssum[t - off] : 0;
        __syncthreads();
        ssum[t] += v;
        __syncthreads();
    }
    int run = (t == 0) ? 0 : ssum[t - 1];
    for (int i = b0; i < b1; i++) {
        int c = cnt[i];
        ptr[i] = run;
        cur[i] = run;
        cnt[i] = 0;
        run += c;
    }
    if (t == 1023) ptr[n] = ssum[1023];
}

__global__ void k_scatter(const int* __restrict__ dst_ab, const int* __restrict__ src_ab,
                          const float* __restrict__ val_ab,
                          const int* __restrict__ dst_ba, const int* __restrict__ src_ba,
                          const float* __restrict__ val_ba) {
    int e = blockIdx.x * blockDim.x + threadIdx.x;
    if (e < EE) {
        int p = atomicAdd(&g_cur_ab[dst_ab[e]], 1);
        g_srcs_ab[p] = src_ab[e];
        g_vals_ab[p] = val_ab[e];
        p = atomicAdd(&g_cur_ba[dst_ba[e]], 1);
        g_srcs_ba[p] = src_ba[e];
        g_vals_ba[p] = val_ba[e];
    }
}

// ---------------- spmm + fused l2norm ----------------
__global__ void k_spmm_ab(const float* __restrict__ feat_A) {
    int w = (blockIdx.x * blockDim.x + threadIdx.x) >> 5;
    int lane = threadIdx.x & 31;
    if (w >= N_B * VV) return;
    int n = w >> 1, v = w & 1;
    int beg = g_ptr_ab[n], end = g_ptr_ab[n + 1];
    float4 acc = make_float4(0.f, 0.f, 0.f, 0.f);
    for (int c = beg; c < end; c += 32) {
        int m = min(32, end - c);
        int s = 0; float vv = 0.f;
        if (lane < m) { s = g_srcs_ab[c + lane]; vv = g_vals_ab[c + lane]; }
        int j = 0;
        for (; j + 4 <= m; j += 4) {
            int s0 = __shfl_sync(0xffffffffu, s, j);
            int s1 = __shfl_sync(0xffffffffu, s, j + 1);
            int s2 = __shfl_sync(0xffffffffu, s, j + 2);
            int s3 = __shfl_sync(0xffffffffu, s, j + 3);
            float u0 = __shfl_sync(0xffffffffu, vv, j);
            float u1 = __shfl_sync(0xffffffffu, vv, j + 1);
            float u2 = __shfl_sync(0xffffffffu, vv, j + 2);
            float u3 = __shfl_sync(0xffffffffu, vv, j + 3);
            const float4 f0 = *reinterpret_cast<const float4*>(feat_A + (((size_t)s0 * VV + v) << 7) + (lane << 2));
            const float4 f1 = *reinterpret_cast<const float4*>(feat_A + (((size_t)s1 * VV + v) << 7) + (lane << 2));
            const float4 f2 = *reinterpret_cast<const float4*>(feat_A + (((size_t)s2 * VV + v) << 7) + (lane << 2));
            const float4 f3 = *reinterpret_cast<const float4*>(feat_A + (((size_t)s3 * VV + v) << 7) + (lane << 2));
            acc.x = fmaf(f0.x, u0, acc.x); acc.y = fmaf(f0.y, u0, acc.y);
            acc.z = fmaf(f0.z, u0, acc.z); acc.w = fmaf(f0.w, u0, acc.w);
            acc.x = fmaf(f1.x, u1, acc.x); acc.y = fmaf(f1.y, u1, acc.y);
            acc.z = fmaf(f1.z, u1, acc.z); acc.w = fmaf(f1.w, u1, acc.w);
            acc.x = fmaf(f2.x, u2, acc.x); acc.y = fmaf(f2.y, u2, acc.y);
            acc.z = fmaf(f2.z, u2, acc.z); acc.w = fmaf(f2.w, u2, acc.w);
            acc.x = fmaf(f3.x, u3, acc.x); acc.y = fmaf(f3.y, u3, acc.y);
            acc.z = fmaf(f3.z, u3, acc.z); acc.w = fmaf(f3.w, u3, acc.w);
        }
        for (; j < m; j++) {
            int sj = __shfl_sync(0xffffffffu, s, j);
            float vj = __shfl_sync(0xffffffffu, vv, j);
            const float4 f = *reinterpret_cast<const float4*>(feat_A + (((size_t)sj * VV + v) << 7) + (lane << 2));
            acc.x = fmaf(f.x, vj, acc.x); acc.y = fmaf(f.y, vj, acc.y);
            acc.z = fmaf(f.z, vj, acc.z); acc.w = fmaf(f.w, vj, acc.w);
        }
    }
    float sq = warp_sum(acc.x * acc.x + acc.y * acc.y + acc.z * acc.z + acc.w * acc.w);
    float inv = 1.f / fmaxf(sqrtf(sq), 1e-12f);
    *reinterpret_cast<float4*>(g_hB + (((size_t)n * VV + v) << 7) + (lane << 2)) =
        make_float4(acc.x * inv, acc.y * inv, acc.z * inv, acc.w * inv);
}

__global__ void k_spmm_ba(const float* __restrict__ feat_B) {
    int w = (blockIdx.x * blockDim.x + threadIdx.x) >> 5;
    int lane = threadIdx.x & 31;
    if (w >= N_A * VV) return;
    int n = w >> 1, v = w & 1;
    int beg = g_ptr_ba[n], end = g_ptr_ba[n + 1];
    float4 a1 = make_float4(0.f, 0.f, 0.f, 0.f);
    float4 a2 = make_float4(0.f, 0.f, 0.f, 0.f);
    for (int c = beg; c < end; c += 32) {
        int m = min(32, end - c);
        int s = 0; float vv = 0.f;
        if (lane < m) { s = g_srcs_ba[c + lane]; vv = g_vals_ba[c + lane]; }
        int j = 0;
        for (; j + 2 <= m; j += 2) {
            int s0 = __shfl_sync(0xffffffffu, s, j);
            int s1 = __shfl_sync(0xffffffffu, s, j + 1);
            float u0 = __shfl_sync(0xffffffffu, vv, j);
            float u1 = __shfl_sync(0xffffffffu, vv, j + 1);
            size_t o0 = (((size_t)s0 * VV + v) << 7) + (lane << 2);
            size_t o1 = (((size_t)s1 * VV + v) << 7) + (lane << 2);
            const float4 p0 = *reinterpret_cast<const float4*>(g_hB + o0);
            const float4 q0 = *reinterpret_cast<const float4*>(feat_B + o0);
            const float4 p1 = *reinterpret_cast<const float4*>(g_hB + o1);
            const float4 q1 = *reinterpret_cast<const float4*>(feat_B + o1);
            a1.x = fmaf(p0.x, u0, a1.x); a1.y = fmaf(p0.y, u0, a1.y);
            a1.z = fmaf(p0.z, u0, a1.z); a1.w = fmaf(p0.w, u0, a1.w);
            a2.x = fmaf(q0.x, u0, a2.x); a2.y = fmaf(q0.y, u0, a2.y);
            a2.z = fmaf(q0.z, u0, a2.z); a2.w = fmaf(q0.w, u0, a2.w);
            a1.x = fmaf(p1.x, u1, a1.x); a1.y = fmaf(p1.y, u1, a1.y);
            a1.z = fmaf(p1.z, u1, a1.z); a1.w = fmaf(p1.w, u1, a1.w);
            a2.x = fmaf(q1.x, u1, a2.x); a2.y = fmaf(q1.y, u1, a2.y);
            a2.z = fmaf(q1.z, u1, a2.z); a2.w = fmaf(q1.w, u1, a2.w);
        }
        for (; j < m; j++) {
            int sj = __shfl_sync(0xffffffffu, s, j);
            float vj = __shfl_sync(0xffffffffu, vv, j);
            size_t off = (((size_t)sj * VV + v) << 7) + (lane << 2);
            const float4 f1 = *reinterpret_cast<const float4*>(g_hB + off);
            const float4 f2 = *reinterpret_cast<const float4*>(feat_B + off);
            a1.x = fmaf(f1.x, vj, a1.x); a1.y = fmaf(f1.y, vj, a1.y);
            a1.z = fmaf(f1.z, vj, a1.z); a1.w = fmaf(f1.w, vj, a1.w);
            a2.x = fmaf(f2.x, vj, a2.x); a2.y = fmaf(f2.y, vj, a2.y);
            a2.z = fmaf(f2.z, vj, a2.z); a2.w = fmaf(f2.w, vj, a2.w);
        }
    }
    size_t outoff = (((size_t)n * VV + v) << 7) + (lane << 2);
    float sq1 = warp_sum(a1.x * a1.x + a1.y * a1.y + a1.z * a1.z + a1.w * a1.w);
    float i1 = 1.f / fmaxf(sqrtf(sq1), 1e-12f);
    *reinterpret_cast<float4*>(g_hABA + outoff) =
        make_float4(a1.x * i1, a1.y * i1, a1.z * i1, a1.w * i1);
    float sq2 = warp_sum(a2.x * a2.x + a2.y * a2.y + a2.z * a2.z + a2.w * a2.w);
    float i2 = 1.f / fmaxf(sqrtf(sq2), 1e-12f);
    *reinterpret_cast<float4*>(g_hBA + outoff) =
        make_float4(a2.x * i2, a2.y * i2, a2.z * i2, a2.w * i2);
}

// ---------------- mma.sync proj (both matrices): relu(LN(in @ W^T + b)) -> g_x ----------------
__global__ void __launch_bounds__(256) k_proj_mma(
        const float* __restrict__ W1m, const float* __restrict__ b1m,
        const float* __restrict__ g1m, const float* __restrict__ be1m,
        const float* __restrict__ W2m, const float* __restrict__ b2m,
        const float* __restrict__ g2m, const float* __restrict__ be2m) {
    extern __shared__ char smc[];
    unsigned sbase = smem_u32(smc);
    int tid = threadIdx.x, wid = tid >> 5, lane = tid & 31;

    stage_W(smc, 0,     32768, W1m, tid, 256);
    stage_W(smc, 65536, 98304, W2m, tid, 256);
    float* sB = reinterpret_cast<float*>(smc + PROJ_BOFF2);
    if (tid < 128) {
        sB[tid]       = b1m[tid];  sB[128 + tid] = g1m[tid];  sB[256 + tid] = be1m[tid];
        sB[384 + tid] = b2m[tid];  sB[512 + tid] = g2m[tid];  sB[640 + tid] = be2m[tid];
    }
    __syncthreads();

    int aoff = PROJ_AOFF + wid * 8192;
    unsigned aBaseH = sbase + aoff, aBaseL = aBaseH + 4096;
    const int NTH = ROWS_H / 16;   // 3750
    const int c0 = 2 * (lane & 3);
    const int r0 = lane >> 2;
    for (int t = blockIdx.x * 8 + wid; t < 2 * NTH; t += GRID_GEMM * 8) {
        int which = (t >= NTH) ? 1 : 0;
        int base = (which ? (t - NTH) : t) * 16;
        const float* src = (which ? g_hBA : g_hABA) + (size_t)base * DD;
        stage_A16(smc, aoff, aoff + 4096, src, lane);
        __syncwarp();

        float acc[16][4];
#pragma unroll
        for (int nb = 0; nb < 16; nb++) {
            acc[nb][0] = acc[nb][1] = acc[nb][2] = acc[nb][3] = 0.f;
        }
        unsigned wH = sbase + which * 65536, wL = wH + 32768;
        mma_core(acc, aBaseH, aBaseL, wH, wL, lane);

        const float* bb = sB + which * 384;
        const float* gg = bb + 128;
        const float* ee = bb + 256;
        float s0 = 0.f, q0 = 0.f, s1 = 0.f, q1 = 0.f;
#pragma unroll
        for (int nb = 0; nb < 16; nb++) {
            int c = nb * 8 + c0;
            float bv0 = bb[c], bv1 = bb[c + 1];
            acc[nb][0] += bv0; acc[nb][1] += bv1;
            acc[nb][2] += bv0; acc[nb][3] += bv1;
            s0 += acc[nb][0] + acc[nb][1];
            q0 += acc[nb][0] * acc[nb][0] + acc[nb][1] * acc[nb][1];
            s1 += acc[nb][2] + acc[nb][3];
            q1 += acc[nb][2] * acc[nb][2] + acc[nb][3] * acc[nb][3];
        }
        s0 += __shfl_xor_sync(0xffffffffu, s0, 1); s0 += __shfl_xor_sync(0xffffffffu, s0, 2);
        q0 += __shfl_xor_sync(0xffffffffu, q0, 1); q0 += __shfl_xor_sync(0xffffffffu, q0, 2);
        s1 += __shfl_xor_sync(0xffffffffu, s1, 1); s1 += __shfl_xor_sync(0xffffffffu, s1, 2);
        q1 += __shfl_xor_sync(0xffffffffu, q1, 1); q1 += __shfl_xor_sync(0xffffffffu, q1, 2);
        float mu0 = s0 * (1.f / DD), rs0 = rsqrtf(q0 * (1.f / DD) - mu0 * mu0 + 1e-5f);
        float mu1 = s1 * (1.f / DD), rs1 = rsqrtf(q1 * (1.f / DD) - mu1 * mu1 + 1e-5f);

        float* o0 = g_x + ((size_t)(base + r0) * PP + which) * DD;
        float* o1 = g_x + ((size_t)(base + r0 + 8) * PP + which) * DD;
#pragma unroll
        for (int nb = 0; nb < 16; nb++) {
            int c = nb * 8 + c0;
            float g0v = gg[c], g1v = gg[c + 1], e0v = ee[c], e1v = ee[c + 1];
            *reinterpret_cast<float2*>(o0 + c) = make_float2(
                fmaxf((acc[nb][0] - mu0) * rs0 * g0v + e0v, 0.f),
                fmaxf((acc[nb][1] - mu0) * rs0 * g1v + e1v, 0.f));
            *reinterpret_cast<float2*>(o1 + c) = make_float2(
                fmaxf((acc[nb][2] - mu1) * rs1 * g0v + e0v, 0.f),
                fmaxf((acc[nb][3] - mu1) * rs1 * g1v + e1v, 0.f));
        }
        __syncwarp();
    }
}

// ---------------- mma.sync fused qkv + per-head attention -> g_o ----------------
__global__ void __launch_bounds__(256) k_qkv_mma(const float* __restrict__ Win,
                                                 const float* __restrict__ bin_) {
    extern __shared__ char smc[];
    unsigned sbase = smem_u32(smc);
    int tid = threadIdx.x, wid = tid >> 5, lane = tid & 31;

    stage_W(smc, 0,      32768,  Win,               tid, 256);   // Wq
    stage_W(smc, 65536,  98304,  Win + DD * DD,     tid, 256);   // Wk
    stage_W(smc, 131072, 163840, Win + 2 * DD * DD, tid, 256);   // Wv
    float* sB = reinterpret_cast<float*>(smc + QKV_BOFF);
    if (tid < 128) {
        sB[tid] = bin_[tid];
        sB[128 + tid] = bin_[DD + tid];
        sB[256 + tid] = bin_[2 * DD + tid];
    }
    __syncthreads();

    int pairId = wid >> 1, half = wid & 1;
    int aoff = QKV_AOFF + pairId * 8192;
    unsigned aBaseH = sbase + aoff, aBaseL = aBaseH + 4096;
    unsigned wq = sbase, wk = sbase + 65536, wv = sbase + 131072;
    const float qscale = 0.17677669529663687f;
    const int NT = ROWS_X / 16;           // 7500
    const int PAIRS = GRID_GEMM * 4;      // 592
    const int NITER = (NT + PAIRS - 1) / PAIRS;   // 13
    const int c0 = 2 * (lane & 3);
    const int r0 = lane >> 2;
    int gp = blockIdx.x * 4 + pairId;
    for (int it = 0; it < NITER; it++) {
        int t = gp + it * PAIRS;
        bool active = (t < NT);
        int base = active ? t * 16 : 0;
        if (active) {
            const float* src = g_x + (size_t)base * DD;
            int l64 = half * 32 + lane;
#pragma unroll
            for (int i = 0; i < 8; i++) {
                int idx = l64 + i * 64;
                int r = idx >> 5;
                int kq = (idx & 31) << 2;
                float4 f = *reinterpret_cast<const float4*>(src + (size_t)r * DD + kq);
                u64 hi, lo; split4(f, hi, lo);
                unsigned off = (unsigned)(((kq >> 4) * 512) +
                                          ((((r >> 3) | (((kq >> 3) & 1) << 1))) * 128) +
                                          ((r & 7) * 16) + ((kq & 7) * 2));
                *reinterpret_cast<u64*>(smc + aoff + off) = hi;
                *reinterpret_cast<u64*>(smc + aoff + 4096 + off) = lo;
            }
        }
        __syncthreads();
        if (active) {
            unsigned ah[8][4], al[8][4];
#pragma unroll
            for (int kb = 0; kb < 8; kb++) {
                ldsm4(ah[kb], aBaseH + kb * 512 + lane * 16);
                ldsm4(al[kb], aBaseL + kb * 512 + lane * 16);
            }
            // phase 1: Q, K for this warp's 8 nb blocks (4 nbp groups)
            float q[8][4], k[8][4];
#pragma unroll
            for (int nbl = 0; nbl < 8; nbl++) {
                q[nbl][0] = q[nbl][1] = q[nbl][2] = q[nbl][3] = 0.f;
                k[nbl][0] = k[nbl][1] = k[nbl][2] = k[nbl][3] = 0.f;
            }
#pragma unroll
            for (int kb = 0; kb < 8; kb++) {
#pragma unroll
                for (int nbpl = 0; nbpl < 4; nbpl++) {
                    int nbp = half * 4 + nbpl;
                    unsigned boff = (unsigned)((nbp * 8 + kb) * 512 + lane * 16);
                    unsigned qh[4], ql[4], kh[4], kl[4];
                    ldsm4(qh, wq + boff);
                    ldsm4(ql, wq + 32768 + boff);
                    ldsm4(kh, wk + boff);
                    ldsm4(kl, wk + 32768 + boff);
                    int b0i = 2 * nbpl, b1i = 2 * nbpl + 1;
                    mma16816(q[b0i], ah[kb], qh[0], qh[1]);
                    mma16816(q[b1i], ah[kb], qh[2], qh[3]);
                    mma16816(k[b0i], ah[kb], kh[0], kh[1]);
                    mma16816(k[b1i], ah[kb], kh[2], kh[3]);
                    mma16816(q[b0i], ah[kb], ql[0], ql[1]);
                    mma16816(q[b1i], ah[kb], ql[2], ql[3]);
                    mma16816(k[b0i], ah[kb], kl[0], kl[1]);
                    mma16816(k[b1i], ah[kb], kl[2], kl[3]);
                    mma16816(q[b0i], al[kb], qh[0], qh[1]);
                    mma16816(q[b1i], al[kb], qh[2], qh[3]);
                    mma16816(k[b0i], al[kb], kh[0], kh[1]);
                    mma16816(k[b1i], al[kb], kh[2], kh[3]);
                }
            }
            // biases
#pragma unroll
            for (int nbl = 0; nbl < 8; nbl++) {
                int c = (half * 8 + nbl) * 8 + c0;
                float bq0 = sB[c], bq1 = sB[c + 1];
                float bk0 = sB[128 + c], bk1 = sB[128 + c + 1];
                q[nbl][0] += bq0; q[nbl][1] += bq1; q[nbl][2] += bq0; q[nbl][3] += bq1;
                k[nbl][0] += bk0; k[nbl][1] += bk1; k[nbl][2] += bk0; k[nbl][3] += bk1;
            }
            // per-head scores + softmax (2 local heads); partner row via shfl_xor(4)
            float aw[8];
#pragma unroll
            for (int hl = 0; hl < 2; hl++) {
                float pss0 = 0.f, psp0 = 0.f, pss1 = 0.f, psp1 = 0.f;
#pragma unroll
                for (int i = 0; i < 4; i++) {
                    int nbl = hl * 4 + i;
                    float kp0 = __shfl_xor_sync(0xffffffffu, k[nbl][0], 4);
                    float kp1 = __shfl_xor_sync(0xffffffffu, k[nbl][1], 4);
                    float kp2 = __shfl_xor_sync(0xffffffffu, k[nbl][2], 4);
                    float kp3 = __shfl_xor_sync(0xffffffffu, k[nbl][3], 4);
                    pss0 += q[nbl][0] * k[nbl][0] + q[nbl][1] * k[nbl][1];
                    psp0 += q[nbl][0] * kp0 + q[nbl][1] * kp1;
                    pss1 += q[nbl][2] * k[nbl][2] + q[nbl][3] * k[nbl][3];
                    psp1 += q[nbl][2] * kp2 + q[nbl][3] * kp3;
                }
                pss0 += __shfl_xor_sync(0xffffffffu, pss0, 1);
                pss0 += __shfl_xor_sync(0xffffffffu, pss0, 2);
                psp0 += __shfl_xor_sync(0xffffffffu, psp0, 1);
                psp0 += __shfl_xor_sync(0xffffffffu, psp0, 2);
                pss1 += __shfl_xor_sync(0xffffffffu, pss1, 1);
                pss1 += __shfl_xor_sync(0xffffffffu, pss1, 2);
                psp1 += __shfl_xor_sync(0xffffffffu, psp1, 1);
                psp1 += __shfl_xor_sync(0xffffffffu, psp1, 2);
                pss0 *= qscale; psp0 *= qscale; pss1 *= qscale; psp1 *= qscale;
                float m0 = fmaxf(pss0, psp0), m1 = fmaxf(pss1, psp1);
                float es0 = expf(pss0 - m0), ep0 = expf(psp0 - m0);
                float es1 = expf(pss1 - m1), ep1 = expf(psp1 - m1);
                float i0 = 1.f / (es0 + ep0), i1 = 1.f / (es1 + ep1);
                aw[hl * 4 + 0] = es0 * i0;
                aw[hl * 4 + 1] = ep0 * i0;
                aw[hl * 4 + 2] = es1 * i1;
                aw[hl * 4 + 3] = ep1 * i1;
            }
            // phase 2: V
            float v[8][4];
#pragma unroll
            for (int nbl = 0; nbl < 8; nbl++) {
                v[nbl][0] = v[nbl][1] = v[nbl][2] = v[nbl][3] = 0.f;
            }
#pragma unroll
            for (int kb = 0; kb < 8; kb++) {
#pragma unroll
                for (int nbpl = 0; nbpl < 4; nbpl++) {
                    int nbp = half * 4 + nbpl;
                    unsigned boff = (unsigned)((nbp * 8 + kb) * 512 + lane * 16);
                    unsigned vh[4], vl[4];
                    ldsm4(vh, wv + boff);
                    ldsm4(vl, wv + 32768 + boff);
                    int b0i = 2 * nbpl, b1i = 2 * nbpl + 1;
                    mma16816(v[b0i], ah[kb], vh[0], vh[1]);
                    mma16816(v[b1i], ah[kb], vh[2], vh[3]);
                    mma16816(v[b0i], ah[kb], vl[0], vl[1]);
                    mma16816(v[b1i], ah[kb], vl[2], vl[3]);
                    mma16816(v[b0i], al[kb], vh[0], vh[1]);
                    mma16816(v[b1i], al[kb], vh[2], vh[3]);
                }
            }
            // combine: o = a_ss*v_self + a_sp*v_partner, write g_o
            float* o0row = g_o + (size_t)(base + r0) * DD;
            float* o1row = g_o + (size_t)(base + r0 + 8) * DD;
#pragma unroll
            for (int nbl = 0; nbl < 8; nbl++) {
                int c = (half * 8 + nbl) * 8 + c0;
                int hl = nbl >> 2;
                float bv0 = sB[256 + c], bv1 = sB[256 + c + 1];
                float v0 = v[nbl][0] + bv0, v1 = v[nbl][1] + bv1;
                float v2 = v[nbl][2] + bv0, v3 = v[nbl][3] + bv1;
                float vp0 = __shfl_xor_sync(0xffffffffu, v0, 4);
                float vp1 = __shfl_xor_sync(0xffffffffu, v1, 4);
                float vp2 = __shfl_xor_sync(0xffffffffu, v2, 4);
                float vp3 = __shfl_xor_sync(0xffffffffu, v3, 4);
                *reinterpret_cast<float2*>(o0row + c) = make_float2(
                    aw[hl * 4 + 0] * v0 + aw[hl * 4 + 1] * vp0,
                    aw[hl * 4 + 0] * v1 + aw[hl * 4 + 1] * vp1);
                *reinterpret_cast<float2*>(o1row + c) = make_float2(
                    aw[hl * 4 + 2] * v2 + aw[hl * 4 + 3] * vp2,
                    aw[hl * 4 + 2] * v3 + aw[hl * 4 + 3] * vp3);
            }
        }
        __syncthreads();
    }
}

// ---------------- mma.sync out: g_o @ Wout^T + bout; LN(+g_x); mean over P -> d_out ----------------
__global__ void __launch_bounds__(256) k_out_mma(
        const float* __restrict__ Wm, const float* __restrict__ bm,
        const float* __restrict__ gm, const float* __restrict__ bem,
        float* __restrict__ outp) {
    extern __shared__ char smc[];
    unsigned sbase = smem_u32(smc);
    int tid = threadIdx.x, wid = tid >> 5, lane = tid & 31;

    stage_W(smc, 0, 32768, Wm, tid, 256);
    float* sB = reinterpret_cast<float*>(smc + OUT_BOFF2);
    if (tid < 128) {
        sB[tid] = bm[tid];  sB[128 + tid] = gm[tid];  sB[256 + tid] = bem[tid];
    }
    __syncthreads();

    int aoff = OUT_AOFF + wid * 8192;
    unsigned aBaseH = sbase + aoff, aBaseL = aBaseH + 4096;
    unsigned wH = sbase, wL = sbase + 32768;
    const int NT = ROWS_X / 16;
    const int c0 = 2 * (lane & 3);
    const int r0 = lane >> 2;
    const bool store = (lane & 4) == 0;
    for (int t = blockIdx.x * 8 + wid; t < NT; t += GRID_GEMM * 8) {
        int base = t * 16;
        stage_A16(smc, aoff, aoff + 4096, g_o + (size_t)base * DD, lane);
        __syncwarp();

        float acc[16][4];
#pragma unroll
        for (int nb = 0; nb < 16; nb++) {
            acc[nb][0] = acc[nb][1] = acc[nb][2] = acc[nb][3] = 0.f;
        }
        mma_core(acc, aBaseH, aBaseL, wH, wL, lane);

        const float* xr0 = g_x + (size_t)(base + r0) * DD;
        const float* xr1 = g_x + (size_t)(base + r0 + 8) * DD;
        float s0 = 0.f, q0 = 0.f, s1 = 0.f, q1 = 0.f;
#pragma unroll
        for (int nb = 0; nb < 16; nb++) {
            int c = nb * 8 + c0;
            float2 x0 = *reinterpret_cast<const float2*>(xr0 + c);
            float2 x1 = *reinterpret_cast<const float2*>(xr1 + c);
            float bv0 = sB[c], bv1 = sB[c + 1];
            acc[nb][0] += bv0 + x0.x;  acc[nb][1] += bv1 + x0.y;
            acc[nb][2] += bv0 + x1.x;  acc[nb][3] += bv1 + x1.y;
            s0 += acc[nb][0] + acc[nb][1];
            q0 += acc[nb][0] * acc[nb][0] + acc[nb][1] * acc[nb][1];
            s1 += acc[nb][2] + acc[nb][3];
            q1 += acc[nb][2] * acc[nb][2] + acc[nb][3] * acc[nb][3];
        }
        s0 += __shfl_xor_sync(0xffffffffu, s0, 1); s0 += __shfl_xor_sync(0xffffffffu, s0, 2);
        q0 += __shfl_xor_sync(0xffffffffu, q0, 1); q0 += __shfl_xor_sync(0xffffffffu, q0, 2);
        s1 += __shfl_xor_sync(0xffffffffu, s1, 1); s1 += __shfl_xor_sync(0xffffffffu, s1, 2);
        q1 += __shfl_xor_sync(0xffffffffu, q1, 1); q1 += __shfl_xor_sync(0xffffffffu, q1, 2);
        float mu0 = s0 * (1.f / DD), rs0 = rsqrtf(q0 * (1.f / DD) - mu0 * mu0 + 1e-5f);
        float mu1 = s1 * (1.f / DD), rs1 = rsqrtf(q1 * (1.f / DD) - mu1 * mu1 + 1e-5f);

        float* u0 = outp + (size_t)((base + r0) >> 1) * DD;
        float* u1 = outp + (size_t)((base + r0 + 8) >> 1) * DD;
#pragma unroll
        for (int nb = 0; nb < 16; nb++) {
            int c = nb * 8 + c0;
            float g0v = sB[128 + c], g1v = sB[128 + c + 1];
            float e0v = sB[256 + c], e1v = sB[256 + c + 1];
            float y00 = (acc[nb][0] - mu0) * rs0 * g0v + e0v;
            float y01 = (acc[nb][1] - mu0) * rs0 * g1v + e1v;
            float y10 = (acc[nb][2] - mu1) * rs1 * g0v + e0v;
            float y11 = (acc[nb][3] - mu1) * rs1 * g1v + e1v;
            float z00 = 0.5f * (y00 + __shfl_xor_sync(0xffffffffu, y00, 4));
            float z01 = 0.5f * (y01 + __shfl_xor_sync(0xffffffffu, y01, 4));
            float z10 = 0.5f * (y10 + __shfl_xor_sync(0xffffffffu, y10, 4));
            float z11 = 0.5f * (y11 + __shfl_xor_sync(0xffffffffu, y11, 4));
            if (store) {
                *reinterpret_cast<float2*>(u0 + c) = make_float2(z00, z01);
                *reinterpret_cast<float2*>(u1 + c) = make_float2(z10, z11);
            }
        }
        __syncwarp();
    }
}

// ---------------- launch ----------------
extern "C" void kernel_launch(void* const* d_in, const int* in_sizes, int n_in,
                              void* d_out, int out_size) {
    (void)in_sizes; (void)n_in; (void)out_size;
    const float* feat_A = (const float*)d_in[0];
    const float* feat_B = (const float*)d_in[1];
    const int*   src_ab = (const int*)d_in[2];
    const int*   dst_ab = (const int*)d_in[3];
    const float* val_ab = (const float*)d_in[4];
    const int*   src_ba = (const int*)d_in[5];
    const int*   dst_ba = (const int*)d_in[6];
    const float* val_ba = (const float*)d_in[7];
    const float* W1  = (const float*)d_in[8];
    const float* b1  = (const float*)d_in[9];
    const float* g1  = (const float*)d_in[10];
    const float* be1 = (const float*)d_in[11];
    const float* W2  = (const float*)d_in[12];
    const float* b2  = (const float*)d_in[13];
    const float* g2  = (const float*)d_in[14];
    const float* be2 = (const float*)d_in[15];
    const float* Win  = (const float*)d_in[16];
    const float* bin_ = (const float*)d_in[17];
    const float* Wout = (const float*)d_in[18];
    const float* bout = (const float*)d_in[19];
    const float* lng  = (const float*)d_in[20];
    const float* lnb  = (const float*)d_in[21];
    float* outp = (float*)d_out;

    cudaFuncSetAttribute(k_proj_mma, cudaFuncAttributeMaxDynamicSharedMemorySize, SMEM_PROJ_MMA);
    cudaFuncSetAttribute(k_qkv_mma,  cudaFuncAttributeMaxDynamicSharedMemorySize, SMEM_QKV_MMA);
    cudaFuncSetAttribute(k_out_mma,  cudaFuncAttributeMaxDynamicSharedMemorySize, SMEM_OUT_MMA);

    // CSR build (cnt is zero at module load and re-zeroed by k_scan each run)
    k_hist<<<1875, 256>>>(dst_ab, dst_ba);
    k_scan<<<2, 1024>>>();
    k_scatter<<<1875, 256>>>(dst_ab, src_ab, val_ab, dst_ba, src_ba, val_ba);

    // spmm + fused l2norm
    k_spmm_ab<<<7500, 256>>>(feat_A);
    k_spmm_ba<<<7500, 256>>>(feat_B);

    // mma.sync projections -> g_x
    k_proj_mma<<<GRID_GEMM, 256, SMEM_PROJ_MMA>>>(W1, b1, g1, be1, W2, b2, g2, be2);

    // mma.sync fused qkv + per-head attention -> g_o
    k_qkv_mma<<<GRID_GEMM, 256, SMEM_QKV_MMA>>>(Win, bin_);

    // mma.sync out-proj + residual LN + mean -> d_out
    k_out_mma<<<GRID_GEMM, 256, SMEM_OUT_MMA>>>(Wout, bout, lng, lnb, outp);
}